// round 4
// baseline (speedup 1.0000x reference)
#include <cuda_runtime.h>
#include <math.h>

// Scratch for the intermediate h = gelu(x @ w1): [32, 512, 1024] f32 = 64 MB.
__device__ float g_h[32u * 512u * 1024u];
// Normalized subject ids (handles int32 vs int64 input dtype).
__device__ int g_sid[32];

#define BM 128
#define BN 128
#define BK 8
#define TM 8
#define TN 8

// subject_ids arrives either as int32[32] or int64[32] depending on whether
// the reference env had jax x64 enabled. Viewed as int32 words, an int64-LE
// array of ids in [0,64) has every odd word == 0; an int32 array has random
// ids at odd positions (all-zero prob ~ 64^-16). Decide, then normalize.
// Only reads beyond word 31 when the int64 interpretation is confirmed.
__global__ void normalize_sid_kernel(const int* __restrict__ raw) {
    bool is64 = true;
    for (int i = 0; i < 16; i++) {
        if (raw[2 * i + 1] != 0) { is64 = false; break; }
    }
    for (int b = 0; b < 32; b++) {
        int s = is64 ? raw[2 * b] : raw[b];
        // clamp defensively; valid range is [0, 64)
        if (s < 0) s = 0;
        if (s > 63) s = 63;
        g_sid[b] = s;
    }
}

// C[b] = act( A[b] @ W[sid[b]] ) (+ bias[sid[b]])
// A: [B, M, K] row-major, W: [S, K, N] row-major, C: [B, M, N] row-major.
template <bool DO_GELU, bool DO_BIAS>
__global__ __launch_bounds__(256, 2) void subject_sgemm(
    const float* __restrict__ A_base,
    const float* __restrict__ W_base,
    const float* __restrict__ bias_base,
    float* __restrict__ C_base,
    int M, int N, int K)
{
    const int b = blockIdx.z;
    const int s = g_sid[b];
    const float* A = A_base + (size_t)b * M * K;
    const float* W = W_base + (size_t)s * K * N;
    float* C = C_base + (size_t)b * M * N;
    const float* bias = DO_BIAS ? (bias_base + (size_t)s * N) : nullptr;

    __shared__ float As[2][BK][BM];
    __shared__ float Bs[2][BK][BN];

    const int tid = threadIdx.x;
    const int bx = blockIdx.x;  // N tile
    const int by = blockIdx.y;  // M tile

    // 16x16 thread grid, each thread owns an 8x8 micro-tile
    const int tx = tid % 16;
    const int ty = tid / 16;

    // A tile load: [BM=128 rows] x [BK=8 cols], float4 -> 2 threads per row
    const int aRow = tid / 2;
    const int aCol = (tid % 2) * 4;
    // W tile load: [BK=8 rows] x [BN=128 cols], float4 -> 32 threads per row
    const int bRow = tid / 32;
    const int bCol = (tid % 32) * 4;

    const float* Aptr = A + (size_t)(by * BM + aRow) * K + aCol;
    const float* Bptr = W + (size_t)bRow * N + bx * BN + bCol;

    float acc[TM][TN];
    #pragma unroll
    for (int i = 0; i < TM; i++)
        #pragma unroll
        for (int j = 0; j < TN; j++)
            acc[i][j] = 0.0f;

    // Prologue: load tile 0 into buffer 0.
    {
        float4 a4 = *reinterpret_cast<const float4*>(Aptr);
        As[0][aCol + 0][aRow] = a4.x;
        As[0][aCol + 1][aRow] = a4.y;
        As[0][aCol + 2][aRow] = a4.z;
        As[0][aCol + 3][aRow] = a4.w;
        float4 b4 = *reinterpret_cast<const float4*>(Bptr);
        *reinterpret_cast<float4*>(&Bs[0][bRow][bCol]) = b4;
    }
    __syncthreads();

    int buf = 0;
    for (int k0 = 0; k0 < K; k0 += BK) {
        const int nxt = k0 + BK;
        float4 a4n, b4n;
        const bool have_next = (nxt < K);
        if (have_next) {
            a4n = *reinterpret_cast<const float4*>(Aptr + nxt);
            b4n = *reinterpret_cast<const float4*>(Bptr + (size_t)nxt * N);
        }

        #pragma unroll
        for (int k = 0; k < BK; k++) {
            float ar[TM], br[TN];
            #pragma unroll
            for (int i = 0; i < TM; i++) ar[i] = As[buf][k][ty * TM + i];
            #pragma unroll
            for (int j = 0; j < TN; j++) br[j] = Bs[buf][k][tx * TN + j];
            #pragma unroll
            for (int i = 0; i < TM; i++)
                #pragma unroll
                for (int j = 0; j < TN; j++)
                    acc[i][j] = fmaf(ar[i], br[j], acc[i][j]);
        }

        if (have_next) {
            const int nb = buf ^ 1;
            As[nb][aCol + 0][aRow] = a4n.x;
            As[nb][aCol + 1][aRow] = a4n.y;
            As[nb][aCol + 2][aRow] = a4n.z;
            As[nb][aCol + 3][aRow] = a4n.w;
            *reinterpret_cast<float4*>(&Bs[nb][bRow][bCol]) = b4n;
        }
        __syncthreads();
        buf ^= 1;
    }

    #pragma unroll
    for (int i = 0; i < TM; i++) {
        const int row = by * BM + ty * TM + i;
        #pragma unroll
        for (int j = 0; j < TN; j += 4) {
            const int col = bx * BN + tx * TN + j;
            float4 v;
            float vals[4];
            #pragma unroll
            for (int q = 0; q < 4; q++) {
                float xv = acc[i][j + q];
                if (DO_BIAS) xv += bias[col + q];
                if (DO_GELU) {
                    // exact gelu: 0.5*x*(1+erf(x/sqrt(2)))
                    xv = 0.5f * xv * (1.0f + erff(xv * 0.70710678118654752f));
                }
                vals[q] = xv;
            }
            v.x = vals[0]; v.y = vals[1]; v.z = vals[2]; v.w = vals[3];
            *reinterpret_cast<float4*>(C + (size_t)row * N + col) = v;
        }
    }
}

extern "C" void kernel_launch(void* const* d_in, const int* in_sizes, int n_in,
                              void* d_out, int out_size) {
    const float* x = (const float*)d_in[0];     // [32, 512, 512]
    const int* sid_raw = (const int*)d_in[1];   // [32] int32 or int64 (sniffed)
    const float* w1 = (const float*)d_in[2];    // [64, 512, 1024]
    const float* w2 = (const float*)d_in[3];    // [64, 1024, 512]
    const float* bias = (const float*)d_in[4];  // [64, 512]
    float* out = (float*)d_out;                 // [32, 512, 512]

    const int B = 32, T = 512, D = 512, MID = 1024, O = 512;
    (void)in_sizes; (void)n_in; (void)out_size;

    float* hbuf = nullptr;
    cudaGetSymbolAddress((void**)&hbuf, g_h);

    normalize_sid_kernel<<<1, 1>>>(sid_raw);

    // GEMM1 + GELU: h[b] = gelu(x[b] @ w1[sid[b]])  (M=T, N=MID, K=D)
    {
        dim3 grid(MID / BN, T / BM, B);
        subject_sgemm<true, false><<<grid, 256>>>(x, w1, nullptr, hbuf, T, MID, D);
    }
    // GEMM2 + bias: out[b] = h[b] @ w2[sid[b]] + b[sid[b]]  (M=T, N=O, K=MID)
    {
        dim3 grid(O / BN, T / BM, B);
        subject_sgemm<false, true><<<grid, 256>>>(hbuf, w2, bias, out, T, O, MID);
    }
}

// round 6
// speedup vs baseline: 2.6201x; 2.6201x over previous
#include <cuda_runtime.h>
#include <math.h>
#include <stdint.h>

// Scratch for the intermediate h = gelu(x @ w1): [32, 512, 1024] f32 = 64 MB.
__device__ float g_h[32u * 512u * 1024u];
// Normalized subject ids (handles int32 vs int64 input dtype).
__device__ int g_sid[32];

// ---------------------------------------------------------------------------
// sid dtype sniff (int32 vs int64), proven in the passing round-4 kernel.
// ---------------------------------------------------------------------------
__global__ void normalize_sid_kernel(const int* __restrict__ raw) {
    bool is64 = true;
    for (int i = 0; i < 16; i++) {
        if (raw[2 * i + 1] != 0) { is64 = false; break; }
    }
    for (int b = 0; b < 32; b++) {
        int s = is64 ? raw[2 * b] : raw[b];
        if (s < 0) s = 0;
        if (s > 63) s = 63;
        g_sid[b] = s;
    }
}

// ---------------------------------------------------------------------------
// helpers
// ---------------------------------------------------------------------------
__device__ __forceinline__ uint32_t f2tf32(float f) {
    uint32_t u;
    asm("cvt.rna.tf32.f32 %0, %1;" : "=r"(u) : "f"(f));
    return u;
}

__device__ __forceinline__ void mma_tf32(float c[4],
                                         uint32_t a0, uint32_t a1,
                                         uint32_t a2, uint32_t a3,
                                         uint32_t b0, uint32_t b1) {
    asm volatile(
        "mma.sync.aligned.m16n8k8.row.col.f32.tf32.tf32.f32 "
        "{%0,%1,%2,%3}, {%4,%5,%6,%7}, {%8,%9}, {%0,%1,%2,%3};"
        : "+f"(c[0]), "+f"(c[1]), "+f"(c[2]), "+f"(c[3])
        : "r"(a0), "r"(a1), "r"(a2), "r"(a3), "r"(b0), "r"(b1));
}

// ---------------------------------------------------------------------------
// tf32 mma.sync GEMM: C[b] = act( A[b] @ W[sid[b]] ) (+ bias[sid[b]])
//   A: [B, M, K] row-major, W: [S, K, N] row-major, C: [B, M, N] row-major.
//   CTA tile 128x128, BK=16, 256 threads (8 warps: 4(m) x 2(n), warp 32x64).
// ---------------------------------------------------------------------------
#define BK 16
#define APAD 20   // As row stride (floats): 16 + 4 -> conflict-free frag reads
#define BPAD 136  // Bs row stride (floats): 128 + 8 -> conflict-free frag reads

template <bool DO_GELU, bool DO_BIAS>
__global__ __launch_bounds__(256, 2)
void subject_mma_sync(const float* __restrict__ A_base,
                      const float* __restrict__ W_base,
                      const float* __restrict__ bias_base,
                      float* __restrict__ C_base,
                      int M, int N, int K)
{
    const int b = blockIdx.z;
    const int s = g_sid[b];
    const float* A = A_base + (size_t)b * M * K;
    const float* W = W_base + (size_t)s * K * N;
    float* C = C_base + (size_t)b * M * N;
    const int m0 = blockIdx.y * 128;
    const int n0 = blockIdx.x * 128;

    __shared__ uint32_t As[2][128][APAD];  // [m][k], tf32 bits
    __shared__ uint32_t Bs[2][BK][BPAD];   // [k][n], tf32 bits

    const int tid = threadIdx.x;
    const int wid = tid >> 5;
    const int lane = tid & 31;
    const int wm = wid >> 1;   // 0..3 -> 32-row slab
    const int wn = wid & 1;    // 0..1 -> 64-col slab
    const int g = lane >> 2;   // group id 0..7
    const int t4 = lane & 3;   // 0..3

    // Global load mapping (two float4 each for A and B per chunk):
    const int aRow0 = tid >> 2;       // +64 for i=1
    const int aCol4 = tid & 3;        // float4 index along K (BK=16 -> 4)
    const int bK0 = tid >> 5;         // +8 for i=1
    const int bN4 = tid & 31;         // float4 index along N (128 -> 32)

    const float* Ag = A + (size_t)(m0 + aRow0) * K + aCol4 * 4;
    const float* Bg = W + (size_t)bK0 * N + n0 + bN4 * 4;

    float acc[2][8][4];
    #pragma unroll
    for (int i = 0; i < 2; i++)
        #pragma unroll
        for (int j = 0; j < 8; j++)
            #pragma unroll
            for (int q = 0; q < 4; q++)
                acc[i][j][q] = 0.0f;

    const int NC = K / BK;

    float4 av[2], bv[2];

    // ---- prologue: load chunk 0, convert, store to buffer 0 ----
    #pragma unroll
    for (int i = 0; i < 2; i++) {
        av[i] = *reinterpret_cast<const float4*>(Ag + (size_t)(64 * i) * K);
        bv[i] = *reinterpret_cast<const float4*>(Bg + (size_t)(8 * i) * N);
    }
    #pragma unroll
    for (int i = 0; i < 2; i++) {
        uint4 ua = make_uint4(f2tf32(av[i].x), f2tf32(av[i].y),
                              f2tf32(av[i].z), f2tf32(av[i].w));
        *reinterpret_cast<uint4*>(&As[0][aRow0 + 64 * i][aCol4 * 4]) = ua;
        uint4 ub = make_uint4(f2tf32(bv[i].x), f2tf32(bv[i].y),
                              f2tf32(bv[i].z), f2tf32(bv[i].w));
        *reinterpret_cast<uint4*>(&Bs[0][bK0 + 8 * i][bN4 * 4]) = ub;
    }
    __syncthreads();

    for (int c = 0; c < NC; c++) {
        const int p = c & 1;
        const bool more = (c + 1 < NC);

        // Issue next chunk's global loads (latency overlapped with mma).
        if (more) {
            const int k0 = (c + 1) * BK;
            #pragma unroll
            for (int i = 0; i < 2; i++) {
                av[i] = *reinterpret_cast<const float4*>(
                    Ag + (size_t)(64 * i) * K + k0);
                bv[i] = *reinterpret_cast<const float4*>(
                    Bg + (size_t)(k0 + 8 * i) * N);
            }
        }

        // Compute on buffer p: 2 k-steps of m16n8k8.
        #pragma unroll
        for (int ks = 0; ks < 2; ks++) {
            const int kk = ks * 8;
            uint32_t af[2][4];
            #pragma unroll
            for (int fm = 0; fm < 2; fm++) {
                const int mr = wm * 32 + fm * 16 + g;
                af[fm][0] = As[p][mr][kk + t4];
                af[fm][1] = As[p][mr + 8][kk + t4];
                af[fm][2] = As[p][mr][kk + t4 + 4];
                af[fm][3] = As[p][mr + 8][kk + t4 + 4];
            }
            uint32_t bf[8][2];
            #pragma unroll
            for (int fn = 0; fn < 8; fn++) {
                const int nc = wn * 64 + fn * 8 + g;
                bf[fn][0] = Bs[p][kk + t4][nc];
                bf[fn][1] = Bs[p][kk + t4 + 4][nc];
            }
            #pragma unroll
            for (int fm = 0; fm < 2; fm++)
                #pragma unroll
                for (int fn = 0; fn < 8; fn++)
                    mma_tf32(acc[fm][fn],
                             af[fm][0], af[fm][1], af[fm][2], af[fm][3],
                             bf[fn][0], bf[fn][1]);
        }

        if (more) {
            const int q = (c + 1) & 1;
            #pragma unroll
            for (int i = 0; i < 2; i++) {
                uint4 ua = make_uint4(f2tf32(av[i].x), f2tf32(av[i].y),
                                      f2tf32(av[i].z), f2tf32(av[i].w));
                *reinterpret_cast<uint4*>(&As[q][aRow0 + 64 * i][aCol4 * 4]) = ua;
                uint4 ub = make_uint4(f2tf32(bv[i].x), f2tf32(bv[i].y),
                                      f2tf32(bv[i].z), f2tf32(bv[i].w));
                *reinterpret_cast<uint4*>(&Bs[q][bK0 + 8 * i][bN4 * 4]) = ub;
            }
        }
        __syncthreads();
    }

    // ---- epilogue ----
    const float* brow = DO_BIAS ? (bias_base + (size_t)s * N + n0) : nullptr;

    #pragma unroll
    for (int fm = 0; fm < 2; fm++) {
        const int r0 = m0 + wm * 32 + fm * 16 + g;
        #pragma unroll
        for (int fn = 0; fn < 8; fn++) {
            const int col = wn * 64 + fn * 8 + t4 * 2;
            #pragma unroll
            for (int h = 0; h < 2; h++) {  // h=0: rows g, h=1: rows g+8
                const int row = r0 + 8 * h;
                float v0 = acc[fm][fn][2 * h + 0];
                float v1 = acc[fm][fn][2 * h + 1];
                if (DO_BIAS) {
                    v0 += brow[col];
                    v1 += brow[col + 1];
                }
                if (DO_GELU) {
                    v0 = 0.5f * v0 * (1.0f + erff(v0 * 0.70710678118654752f));
                    v1 = 0.5f * v1 * (1.0f + erff(v1 * 0.70710678118654752f));
                }
                float2 v = make_float2(v0, v1);
                *reinterpret_cast<float2*>(C + (size_t)row * N + n0 + col) = v;
            }
        }
    }
}

// ---------------------------------------------------------------------------
extern "C" void kernel_launch(void* const* d_in, const int* in_sizes, int n_in,
                              void* d_out, int out_size) {
    const float* x = (const float*)d_in[0];     // [32, 512, 512]
    const int* sid_raw = (const int*)d_in[1];   // [32] int32 or int64 (sniffed)
    const float* w1 = (const float*)d_in[2];    // [64, 512, 1024]
    const float* w2 = (const float*)d_in[3];    // [64, 1024, 512]
    const float* bias = (const float*)d_in[4];  // [64, 512]
    float* out = (float*)d_out;                 // [32, 512, 512]

    const int B = 32, T = 512, D = 512, MID = 1024, O = 512;
    (void)in_sizes; (void)n_in; (void)out_size;

    float* hbuf = nullptr;
    cudaGetSymbolAddress((void**)&hbuf, g_h);

    normalize_sid_kernel<<<1, 1>>>(sid_raw);

    // GEMM1 + GELU: h[b] = gelu(x[b] @ w1[sid[b]])  (M=512, N=1024, K=512)
    {
        dim3 grid(MID / 128, T / 128, B);
        subject_mma_sync<true, false><<<grid, 256>>>(x, w1, nullptr, hbuf, T, MID, D);
    }
    // GEMM2 + bias: out[b] = h[b] @ w2[sid[b]] + b[sid[b]]  (M=512, N=512, K=1024)
    {
        dim3 grid(O / 128, T / 128, B);
        subject_mma_sync<false, true><<<grid, 256>>>(hbuf, w2, bias, out, T, O, MID);
    }
}

// round 7
// speedup vs baseline: 2.7921x; 1.0656x over previous
#include <cuda_runtime.h>
#include <math.h>
#include <stdint.h>

// Scratch for the intermediate h = gelu(x @ w1): [32, 512, 1024] f32 = 64 MB.
__device__ float g_h[32u * 512u * 1024u];

// ---------------------------------------------------------------------------
// helpers
// ---------------------------------------------------------------------------
__device__ __forceinline__ uint32_t smem_u32(const void* p) {
    uint32_t a;
    asm("{ .reg .u64 t; cvta.to.shared.u64 t, %1; cvt.u32.u64 %0, t; }"
        : "=r"(a) : "l"(p));
    return a;
}

__device__ __forceinline__ uint32_t f2tf32(uint32_t raw_f32_bits) {
    uint32_t u;
    asm("cvt.rna.tf32.f32 %0, %1;" : "=r"(u) : "r"(raw_f32_bits));
    return u;
}

__device__ __forceinline__ void cp_async16(uint32_t saddr, const void* gptr) {
    asm volatile("cp.async.cg.shared.global [%0], [%1], 16;"
                 :: "r"(saddr), "l"(gptr) : "memory");
}
__device__ __forceinline__ void cp_commit() {
    asm volatile("cp.async.commit_group;" ::: "memory");
}
template <int N>
__device__ __forceinline__ void cp_wait() {
    asm volatile("cp.async.wait_group %0;" :: "n"(N) : "memory");
}

__device__ __forceinline__ void mma_tf32(float c[4],
                                         uint32_t a0, uint32_t a1,
                                         uint32_t a2, uint32_t a3,
                                         uint32_t b0, uint32_t b1) {
    asm volatile(
        "mma.sync.aligned.m16n8k8.row.col.f32.tf32.tf32.f32 "
        "{%0,%1,%2,%3}, {%4,%5,%6,%7}, {%8,%9}, {%0,%1,%2,%3};"
        : "+f"(c[0]), "+f"(c[1]), "+f"(c[2]), "+f"(c[3])
        : "r"(a0), "r"(a1), "r"(a2), "r"(a3), "r"(b0), "r"(b1));
}

// sid dtype sniff (int32 vs int64), executed redundantly per thread.
// Viewed as int32 words, int64-LE ids in [0,64) have every odd word == 0.
__device__ __forceinline__ int load_sid(const int* __restrict__ raw, int b) {
    bool is64 = true;
    #pragma unroll
    for (int i = 0; i < 16; i++)
        if (raw[2 * i + 1] != 0) { is64 = false; break; }
    int s = is64 ? raw[2 * b] : raw[b];
    if (s < 0) s = 0;
    if (s > 63) s = 63;
    return s;
}

// ---------------------------------------------------------------------------
// tf32 mma.sync GEMM, cp.async 3-stage pipeline.
//   C[b] = act( A[b] @ W[sid[b]] ) (+ bias[sid[b]])
//   A: [B, M, K] row-major, W: [S, K, N] row-major, C: [B, M, N] row-major.
//   CTA tile 128x128, BK=16, 128 threads (4 warps, 2(m) x 2(n), warp 64x64).
// ---------------------------------------------------------------------------
#define BK 16
#define APAD 20   // As row stride (floats): conflict-free A-fragment reads
#define BPAD 136  // Bs row stride (floats): conflict-free B-fragment reads
#define NSTAGE 3

static constexpr int A_STG_F = 128 * APAD;          // floats per A stage
static constexpr int B_STG_F = BK * BPAD;           // floats per B stage
static constexpr int STG_F = A_STG_F + B_STG_F;     // 2560 + 2176 = 4736
static constexpr int SMEM_DYN = NSTAGE * STG_F * 4; // 56832 B

template <bool DO_GELU, bool DO_BIAS>
__global__ __launch_bounds__(128, 2)
void subject_mma_cp(const float* __restrict__ A_base,
                    const float* __restrict__ W_base,
                    const int* __restrict__ sid_raw,
                    const float* __restrict__ bias_base,
                    float* __restrict__ C_base,
                    int M, int N, int K)
{
    const int b = blockIdx.z;
    const int s = load_sid(sid_raw, b);
    const float* A = A_base + (size_t)b * M * K;
    const float* W = W_base + (size_t)s * K * N;
    float* C = C_base + (size_t)b * M * N;
    const int m0 = blockIdx.y * 128;
    const int n0 = blockIdx.x * 128;

    extern __shared__ float dsm[];
    const uint32_t smem0 = smem_u32(dsm);

    const int tid = threadIdx.x;
    const int wid = tid >> 5;
    const int lane = tid & 31;
    const int wm = wid >> 1;   // 0..1 -> 64-row slab
    const int wn = wid & 1;    // 0..1 -> 64-col slab
    const int g = lane >> 2;   // 0..7
    const int t4 = lane & 3;   // 0..3

    // cp.async mapping:
    //  A stage: 128 rows x 16 cols. thread -> row (tid>>2)+32i, quad tid&3.
    //  B stage: 16 rows x 128 cols. thread -> row (tid>>5)+4i, quad tid&31.
    const int aR = tid >> 2, aQ = tid & 3;
    const int bR = tid >> 5, bQ = tid & 31;
    const float* AgBase = A + (size_t)(m0 + aR) * K + aQ * 4;
    const float* BgBase = W + (size_t)bR * N + n0 + bQ * 4;

    const int NC = K / BK;

    auto issue_stage = [&](int c) {
        const uint32_t sa = smem0 + (uint32_t)((c % NSTAGE) * STG_F) * 4u;
        const uint32_t sb = sa + (uint32_t)A_STG_F * 4u;
        const int k0 = c * BK;
        #pragma unroll
        for (int i = 0; i < 4; i++) {
            cp_async16(sa + (uint32_t)((aR + 32 * i) * APAD + aQ * 4) * 4u,
                       AgBase + (size_t)(32 * i) * K + k0);
        }
        #pragma unroll
        for (int i = 0; i < 4; i++) {
            cp_async16(sb + (uint32_t)((bR + 4 * i) * BPAD + bQ * 4) * 4u,
                       BgBase + (size_t)(k0 + 4 * i) * N);
        }
    };

    float acc[4][8][4];
    #pragma unroll
    for (int i = 0; i < 4; i++)
        #pragma unroll
        for (int j = 0; j < 8; j++)
            #pragma unroll
            for (int q = 0; q < 4; q++)
                acc[i][j][q] = 0.0f;

    // prologue: fill NSTAGE-1 stages
    #pragma unroll
    for (int c = 0; c < NSTAGE - 1; c++) {
        issue_stage(c);
        cp_commit();
    }

    #pragma unroll 1
    for (int c = 0; c < NC; c++) {
        cp_wait<NSTAGE - 2>();   // stage c complete (this thread's view)
        __syncthreads();         // all threads' copies visible; comp(c-1) done

        // issue stage c+NSTAGE-1 into slot (c-1)%NSTAGE (safe post-sync)
        if (c + NSTAGE - 1 < NC) issue_stage(c + NSTAGE - 1);
        cp_commit();             // keep group count uniform (empty ok)

        const uint32_t sa = smem0 + (uint32_t)((c % NSTAGE) * STG_F) * 4u;
        const float* Asf = (const float*)(dsm) + (size_t)(c % NSTAGE) * STG_F;
        const float* Bsf = Asf + A_STG_F;
        (void)sa;

        #pragma unroll
        for (int ks = 0; ks < 2; ks++) {
            const int kk = ks * 8;
            uint32_t af[4][4];
            #pragma unroll
            for (int fm = 0; fm < 4; fm++) {
                const int mr = wm * 64 + fm * 16 + g;
                af[fm][0] = f2tf32(__float_as_uint(Asf[mr * APAD + kk + t4]));
                af[fm][1] = f2tf32(__float_as_uint(Asf[(mr + 8) * APAD + kk + t4]));
                af[fm][2] = f2tf32(__float_as_uint(Asf[mr * APAD + kk + t4 + 4]));
                af[fm][3] = f2tf32(__float_as_uint(Asf[(mr + 8) * APAD + kk + t4 + 4]));
            }
            uint32_t bf[8][2];
            #pragma unroll
            for (int fn = 0; fn < 8; fn++) {
                const int nc = wn * 64 + fn * 8 + g;
                bf[fn][0] = f2tf32(__float_as_uint(Bsf[(kk + t4) * BPAD + nc]));
                bf[fn][1] = f2tf32(__float_as_uint(Bsf[(kk + t4 + 4) * BPAD + nc]));
            }
            #pragma unroll
            for (int fm = 0; fm < 4; fm++)
                #pragma unroll
                for (int fn = 0; fn < 8; fn++)
                    mma_tf32(acc[fm][fn],
                             af[fm][0], af[fm][1], af[fm][2], af[fm][3],
                             bf[fn][0], bf[fn][1]);
        }
    }

    // ---- epilogue ----
    const float* brow = DO_BIAS ? (bias_base + (size_t)s * N + n0) : nullptr;

    #pragma unroll
    for (int fm = 0; fm < 4; fm++) {
        const int r0 = m0 + wm * 64 + fm * 16 + g;
        #pragma unroll
        for (int fn = 0; fn < 8; fn++) {
            const int col = wn * 64 + fn * 8 + t4 * 2;
            #pragma unroll
            for (int h = 0; h < 2; h++) {
                const int row = r0 + 8 * h;
                float v0 = acc[fm][fn][2 * h + 0];
                float v1 = acc[fm][fn][2 * h + 1];
                if (DO_BIAS) {
                    v0 += brow[col];
                    v1 += brow[col + 1];
                }
                if (DO_GELU) {
                    v0 = 0.5f * v0 * (1.0f + erff(v0 * 0.70710678118654752f));
                    v1 = 0.5f * v1 * (1.0f + erff(v1 * 0.70710678118654752f));
                }
                *reinterpret_cast<float2*>(C + (size_t)row * N + n0 + col) =
                    make_float2(v0, v1);
            }
        }
    }
}

// ---------------------------------------------------------------------------
extern "C" void kernel_launch(void* const* d_in, const int* in_sizes, int n_in,
                              void* d_out, int out_size) {
    const float* x = (const float*)d_in[0];     // [32, 512, 512]
    const int* sid_raw = (const int*)d_in[1];   // [32] int32 or int64 (sniffed)
    const float* w1 = (const float*)d_in[2];    // [64, 512, 1024]
    const float* w2 = (const float*)d_in[3];    // [64, 1024, 512]
    const float* bias = (const float*)d_in[4];  // [64, 512]
    float* out = (float*)d_out;                 // [32, 512, 512]

    const int B = 32, T = 512, D = 512, MID = 1024, O = 512;
    (void)in_sizes; (void)n_in; (void)out_size;

    float* hbuf = nullptr;
    cudaGetSymbolAddress((void**)&hbuf, g_h);

    (void)cudaFuncSetAttribute((const void*)subject_mma_cp<true, false>,
                               cudaFuncAttributeMaxDynamicSharedMemorySize, SMEM_DYN);
    (void)cudaFuncSetAttribute((const void*)subject_mma_cp<false, true>,
                               cudaFuncAttributeMaxDynamicSharedMemorySize, SMEM_DYN);

    // GEMM1 + GELU: h[b] = gelu(x[b] @ w1[sid[b]])  (M=512, N=1024, K=512)
    {
        dim3 grid(MID / 128, T / 128, B);
        subject_mma_cp<true, false><<<grid, 128, SMEM_DYN>>>(
            x, w1, sid_raw, nullptr, hbuf, T, MID, D);
    }
    // GEMM2 + bias: out[b] = h[b] @ w2[sid[b]] + b[sid[b]]  (M=512, N=512, K=1024)
    {
        dim3 grid(O / 128, T / 128, B);
        subject_mma_cp<false, true><<<grid, 128, SMEM_DYN>>>(
            hbuf, w2, sid_raw, bias, out, T, O, MID);
    }
}